// round 9
// baseline (speedup 1.0000x reference)
#include <cuda_runtime.h>
#include <cstdint>

#define N_NODES_C  500000
#define N_EDGES_C  8000000
#define N_GRAPHS_C 1000

#define LOG2E_F 1.4426950408889634f
#define SALPHA_F 1.7580993408473766f          // scale*alpha
#define SLN2_F   0.7282895255054788f          // scale*ln(2)

// Scratch (no cudaMalloc allowed)
__device__ float d_eon[N_NODES_C];
__device__ float d_g[N_GRAPHS_C * 11];
__device__ __align__(16) float d_EW[96];      // folded edge-stage weights (exp2-space)

__device__ __forceinline__ float ex2(float y) {
    float r;
    asm("ex2.approx.f32 %0, %1;" : "=f"(r) : "f"(y));
    return r;
}
// scalar selu from y = x*log2(e) (node/graph kernels)
__device__ __forceinline__ float selu_y(float y) {
    float e   = ex2(fminf(y, 0.0f));
    float lin = fmaxf(y, 0.0f);
    return fmaf(SALPHA_F, e, fmaf(SLN2_F, lin, -SALPHA_F));
}

// ---- packed f32x2 helpers (sm_103a) ----
__device__ __forceinline__ uint64_t pk2(float lo, float hi) {
    uint64_t r; asm("mov.b64 %0, {%1, %2};" : "=l"(r) : "f"(lo), "f"(hi)); return r;
}
__device__ __forceinline__ void upk2(float& lo, float& hi, uint64_t v) {
    asm("mov.b64 {%0, %1}, %2;" : "=f"(lo), "=f"(hi) : "l"(v));
}
__device__ __forceinline__ uint64_t fma2(uint64_t a, uint64_t b, uint64_t c) {
    uint64_t d; asm("fma.rn.f32x2 %0, %1, %2, %3;" : "=l"(d) : "l"(a), "l"(b), "l"(c)); return d;
}
// packed selu on a packed y-pair:
//   m = min(y,0);  selu = SA*2^m + SL*y - SL*m - SA   (exact for y>0 branch up to fma rounding)
__device__ __forceinline__ uint64_t selu2(uint64_t y2, uint64_t SA2, uint64_t SL2,
                                          uint64_t NSL2, uint64_t NSA2) {
    float y0, y1; upk2(y0, y1, y2);
    float m0 = fminf(y0, 0.0f), m1 = fminf(y1, 0.0f);
    float e0 = ex2(m0), e1 = ex2(m1);
    uint64_t em = pk2(e0, e1);
    uint64_t mm = pk2(m0, m1);
    return fma2(SA2, em, fma2(SL2, y2, fma2(NSL2, mm, NSA2)));
}

// ---------------------------------------------------------------------------
__global__ void zero_scratch() {
    int i = blockIdx.x * blockDim.x + threadIdx.x;
    int stride = gridDim.x * blockDim.x;
    float4* p = reinterpret_cast<float4*>(d_eon);
    for (int k = i; k < N_NODES_C / 4; k += stride)
        p[k] = make_float4(0.f, 0.f, 0.f, 0.f);
    for (int k = i; k < N_GRAPHS_C * 11; k += stride)
        d_g[k] = 0.f;
}

// ---------------------------------------------------------------------------
// d_EW layout:
//   [0:20)  pn_w1*L       [20:30) pn_b1*L
//   [30:80) M*L (M = pn_w2 @ ue_w1[1:,:])   [80:85) d*L
//   [85:90) ue_w1[0,:]*L  [90:95) ue_w2     [95] ue_b2
// ---------------------------------------------------------------------------
__global__ void setup_kernel(const float* __restrict__ pn_w1, const float* __restrict__ pn_b1,
                             const float* __restrict__ pn_w2, const float* __restrict__ pn_b2,
                             const float* __restrict__ ue_w1, const float* __restrict__ ue_b1,
                             const float* __restrict__ ue_w2, const float* __restrict__ ue_b2) {
    int t = threadIdx.x;
    if (t < 20) d_EW[t] = pn_w1[t] * LOG2E_F;
    if (t < 10) d_EW[20 + t] = pn_b1[t] * LOG2E_F;
    if (t < 50) {
        int j = t / 5, k = t % 5;
        float m = 0.0f;
        for (int q = 0; q < 10; ++q)
            m += pn_w2[j * 10 + q] * ue_w1[(1 + q) * 5 + k];
        d_EW[30 + t] = m * LOG2E_F;
    }
    if (t < 5) {
        float dd = ue_b1[t];
        for (int q = 0; q < 10; ++q)
            dd += pn_b2[q] * ue_w1[(1 + q) * 5 + t];
        d_EW[80 + t] = dd * LOG2E_F;
        d_EW[85 + t] = ue_w1[t] * LOG2E_F;
        d_EW[90 + t] = ue_w2[t];
    }
    if (t == 0) d_EW[95] = ue_b2[0];
}

// ---------------------------------------------------------------------------
// Edge stage: 4 adjacent edges/thread processed as two packed f32x2 pairs.
// All per-j weights duplicated as packed pairs in shared memory (LDS.128
// yields ready fma2 operands, no pack movs). Accumulators stay packed.
// 4 blocks/SM x 128 thr, reg cap 128 (no spill). QUAD indices [qstart, qend).
// ---------------------------------------------------------------------------
__global__ __launch_bounds__(128, 4) void edge_kernel(
        const float* __restrict__ nodes, const float* __restrict__ edges,
        const int* __restrict__ senders, const int* __restrict__ receivers,
        int qstart, int qend) {
    // packed-duplicated weights
    __shared__ __align__(16) ulonglong2 sJ[10][2];  // [j][0]={wa2,wb2} [j][1]={wc2,m42}
    __shared__ __align__(16) ulonglong2 sMm[10][2]; // [j][0]={m02,m12} [j][1]={m22,m32}
    __shared__ __align__(16) ulonglong2 sUV[5];     // [k]={u2,v2}
    __shared__ __align__(16) ulonglong2 sD[3];      // {d02,d12}{d22,d32}{d42,b22}

    int t = threadIdx.x;
    if (t < 10) {
        float wa = d_EW[t], wb = d_EW[10 + t], wc = d_EW[20 + t];
        float m0 = d_EW[30 + t * 5 + 0], m1 = d_EW[30 + t * 5 + 1];
        float m2 = d_EW[30 + t * 5 + 2], m3 = d_EW[30 + t * 5 + 3];
        float m4 = d_EW[30 + t * 5 + 4];
        float* p = (float*)&sJ[t][0];
        p[0] = wa; p[1] = wa; p[2] = wb; p[3] = wb;
        p[4] = wc; p[5] = wc; p[6] = m4; p[7] = m4;
        float* q = (float*)&sMm[t][0];
        q[0] = m0; q[1] = m0; q[2] = m1; q[3] = m1;
        q[4] = m2; q[5] = m2; q[6] = m3; q[7] = m3;
    }
    if (t < 5) {
        float* p = (float*)&sUV[t];
        p[0] = p[1] = d_EW[85 + t];
        p[2] = p[3] = d_EW[90 + t];
    }
    if (t == 0) {
        float* p = (float*)&sD[0];
#pragma unroll
        for (int k = 0; k < 5; ++k) { p[2 * k] = d_EW[80 + k]; p[2 * k + 1] = d_EW[80 + k]; }
        p[10] = d_EW[95]; p[11] = d_EW[95];
    }
    __syncthreads();

    const uint64_t SA2  = pk2(SALPHA_F,  SALPHA_F);
    const uint64_t SL2  = pk2(SLN2_F,    SLN2_F);
    const uint64_t NSL2 = pk2(-SLN2_F,  -SLN2_F);
    const uint64_t NSA2 = pk2(-SALPHA_F, -SALPHA_F);

    const int4*   r4p = (const int4*)receivers;
    const int4*   s4p = (const int4*)senders;
    const float4* e4p = (const float4*)edges;

    const int stride = gridDim.x * blockDim.x;
    for (int q = qstart + blockIdx.x * blockDim.x + threadIdx.x; q < qend; q += stride) {
        int4   rr = __ldg(r4p + q);
        int4   ss = __ldg(s4p + q);
        float4 ee = __ldg(e4p + q);

        // all 8 random gathers in flight before compute
        float nr0 = __ldg(nodes + rr.x);
        float ns0 = __ldg(nodes + ss.x);
        float nr1 = __ldg(nodes + rr.y);
        float ns1 = __ldg(nodes + ss.y);
        float nr2 = __ldg(nodes + rr.z);
        float ns2 = __ldg(nodes + ss.z);
        float nr3 = __ldg(nodes + rr.w);
        float ns3 = __ldg(nodes + ss.w);

        uint64_t nr01 = pk2(nr0, nr1), ns01 = pk2(ns0, ns1);
        uint64_t nr23 = pk2(nr2, nr3), ns23 = pk2(ns2, ns3);

        uint64_t c01[5], c23[5], b22;
        {
            ulonglong2 d0 = sD[0], d1 = sD[1], d2 = sD[2];
            c01[0] = d0.x; c01[1] = d0.y; c01[2] = d1.x; c01[3] = d1.y; c01[4] = d2.x;
            c23[0] = d0.x; c23[1] = d0.y; c23[2] = d1.x; c23[3] = d1.y; c23[4] = d2.x;
            b22 = d2.y;
        }

#pragma unroll
        for (int j = 0; j < 10; ++j) {
            ulonglong2 w0 = sJ[j][0];    // wa2, wb2
            ulonglong2 w1 = sJ[j][1];    // wc2, m42
            ulonglong2 ma = sMm[j][0];   // m02, m12
            ulonglong2 mb = sMm[j][1];   // m22, m32
            uint64_t y01 = fma2(nr01, w0.x, fma2(ns01, w0.y, w1.x));
            uint64_t y23 = fma2(nr23, w0.x, fma2(ns23, w0.y, w1.x));
            uint64_t h01 = selu2(y01, SA2, SL2, NSL2, NSA2);
            uint64_t h23 = selu2(y23, SA2, SL2, NSL2, NSA2);
            c01[0] = fma2(h01, ma.x, c01[0]);  c23[0] = fma2(h23, ma.x, c23[0]);
            c01[1] = fma2(h01, ma.y, c01[1]);  c23[1] = fma2(h23, ma.y, c23[1]);
            c01[2] = fma2(h01, mb.x, c01[2]);  c23[2] = fma2(h23, mb.x, c23[2]);
            c01[3] = fma2(h01, mb.y, c01[3]);  c23[3] = fma2(h23, mb.y, c23[3]);
            c01[4] = fma2(h01, w1.y, c01[4]);  c23[4] = fma2(h23, w1.y, c23[4]);
        }

        uint64_t ev01 = pk2(ee.x, ee.y), ev23 = pk2(ee.z, ee.w);
#pragma unroll
        for (int it = 0; it < 3; ++it) {
            uint64_t a01 = b22, a23 = b22;
#pragma unroll
            for (int k = 0; k < 5; ++k) {
                ulonglong2 uv = sUV[k];
                uint64_t y01 = fma2(ev01, uv.x, c01[k]);
                uint64_t y23 = fma2(ev23, uv.x, c23[k]);
                a01 = fma2(selu2(y01, SA2, SL2, NSL2, NSA2), uv.y, a01);
                a23 = fma2(selu2(y23, SA2, SL2, NSL2, NSA2), uv.y, a23);
            }
            ev01 = a01; ev23 = a23;
        }
        float ev0, ev1, ev2, ev3;
        upk2(ev0, ev1, ev01);
        upk2(ev2, ev3, ev23);
        atomicAdd(&d_eon[rr.x], ev0);
        atomicAdd(&d_eon[rr.y], ev1);
        atomicAdd(&d_eon[rr.z], ev2);
        atomicAdd(&d_eon[rr.w], ev3);
    }
}

// ---------------------------------------------------------------------------
// Node stage: pe MLP + 3 un iterations, warp-aggregated segment sum into d_g.
// ---------------------------------------------------------------------------
__global__ __launch_bounds__(256) void node_kernel(
        const float* __restrict__ nodes, const int* __restrict__ graph_ids,
        const float* __restrict__ pe_w1, const float* __restrict__ pe_b1,
        const float* __restrict__ pe_w2, const float* __restrict__ pe_b2,
        const float* __restrict__ un_w1, const float* __restrict__ un_b1,
        const float* __restrict__ un_w2, const float* __restrict__ un_b2) {
    float PW1[5], PB1[5], PW2[50], PB2[10];
    float UW1[55], UB1[5], UW2[5], UB2v;
#pragma unroll
    for (int i = 0; i < 5; ++i) {
        PW1[i] = __ldg(pe_w1 + i) * LOG2E_F;
        PB1[i] = __ldg(pe_b1 + i) * LOG2E_F;
        UB1[i] = __ldg(un_b1 + i) * LOG2E_F;
        UW2[i] = __ldg(un_w2 + i);
    }
#pragma unroll
    for (int i = 0; i < 50; ++i) PW2[i] = __ldg(pe_w2 + i);
#pragma unroll
    for (int i = 0; i < 10; ++i) PB2[i] = __ldg(pe_b2 + i);
#pragma unroll
    for (int i = 0; i < 55; ++i) UW1[i] = __ldg(un_w1 + i) * LOG2E_F;
    UB2v = __ldg(un_b2);

    int stride = gridDim.x * blockDim.x;
    for (int n = blockIdx.x * blockDim.x + threadIdx.x; n < N_NODES_C; n += stride) {
        float eon = d_eon[n];
        float v[11];
        float hid[5];
#pragma unroll
        for (int k = 0; k < 5; ++k) hid[k] = selu_y(fmaf(eon, PW1[k], PB1[k]));
#pragma unroll
        for (int j = 0; j < 10; ++j) {
            float acc = PB2[j];
#pragma unroll
            for (int k = 0; k < 5; ++k) acc = fmaf(hid[k], PW2[k * 10 + j], acc);
            v[1 + j] = acc;
        }
        float c[5];
#pragma unroll
        for (int k = 0; k < 5; ++k) {
            float acc = UB1[k];
#pragma unroll
            for (int t = 0; t < 10; ++t) acc = fmaf(v[1 + t], UW1[(1 + t) * 5 + k], acc);
            c[k] = acc;
        }
        float x = nodes[n];
#pragma unroll
        for (int it = 0; it < 3; ++it) {
            float acc = UB2v;
#pragma unroll
            for (int k = 0; k < 5; ++k)
                acc = fmaf(selu_y(fmaf(x, UW1[k], c[k])), UW2[k], acc);
            x = acc;
        }
        v[0] = x;

        int gid = graph_ids[n];
        const unsigned mask = 0xffffffffu;
        int g0 = __shfl_sync(mask, gid, 0);
        bool uni = __all_sync(mask, gid == g0);
        if (uni) {
#pragma unroll
            for (int j = 0; j < 11; ++j) {
                float vv = v[j];
#pragma unroll
                for (int off = 16; off > 0; off >>= 1)
                    vv += __shfl_down_sync(mask, vv, off);
                if ((threadIdx.x & 31) == 0) atomicAdd(&d_g[g0 * 11 + j], vv);
            }
        } else {
#pragma unroll
            for (int j = 0; j < 11; ++j)
                atomicAdd(&d_g[gid * 11 + j], v[j]);
        }
    }
}

// ---------------------------------------------------------------------------
__global__ void graph_kernel(const float* __restrict__ pr_w1, const float* __restrict__ pr_b1,
                             const float* __restrict__ pr_w2, const float* __restrict__ pr_b2,
                             float* __restrict__ out) {
    int g = blockIdx.x * blockDim.x + threadIdx.x;
    if (g >= N_GRAPHS_C) return;
    float gv[11];
#pragma unroll
    for (int i = 0; i < 11; ++i) gv[i] = d_g[g * 11 + i];
    float hid[10];
#pragma unroll
    for (int j = 0; j < 10; ++j) {
        float acc = __ldg(pr_b1 + j) * LOG2E_F;
#pragma unroll
        for (int i = 0; i < 11; ++i)
            acc = fmaf(gv[i], __ldg(pr_w1 + i * 10 + j) * LOG2E_F, acc);
        hid[j] = selu_y(acc);
    }
    float o[10];
    float mx = -1e30f;
#pragma unroll
    for (int k = 0; k < 10; ++k) {
        float acc = __ldg(pr_b2 + k) * LOG2E_F;
#pragma unroll
        for (int j = 0; j < 10; ++j)
            acc = fmaf(hid[j], __ldg(pr_w2 + j * 10 + k) * LOG2E_F, acc);
        o[k] = acc;
        mx = fmaxf(mx, acc);
    }
    float sum = 0.0f;
#pragma unroll
    for (int k = 0; k < 10; ++k) { o[k] = ex2(o[k] - mx); sum += o[k]; }
    float inv = 1.0f / sum;
#pragma unroll
    for (int k = 0; k < 10; ++k) out[g * 10 + k] = o[k] * inv;
}

// ---------------------------------------------------------------------------
extern "C" void kernel_launch(void* const* d_in, const int* in_sizes, int n_in,
                              void* d_out, int out_size) {
    const float* nodes = (const float*)d_in[0];
    const float* edges = (const float*)d_in[1];
    const int *senders, *receivers, *graph_ids;
    const float* w[20];

    if (in_sizes[2] == N_EDGES_C) {
        senders   = (const int*)d_in[2];
        receivers = (const int*)d_in[3];
        graph_ids = (const int*)d_in[4];
        int base = (n_in > 25 && in_sizes[5] == 1) ? 6 : 5;
        for (int i = 0; i < 20; ++i) w[i] = (const float*)d_in[base + i];
    } else {
        for (int i = 0; i < 20; ++i) w[i] = (const float*)d_in[2 + i];
        senders   = (const int*)d_in[22];
        receivers = (const int*)d_in[23];
        graph_ids = (const int*)d_in[24];
    }

    // idx 0 zero, 1 setup, 2..5 edge chunks, 6 node, 7 graph.
    zero_scratch<<<232, 256>>>();
    setup_kernel<<<1, 64>>>(w[0], w[1], w[2], w[3], w[4], w[5], w[6], w[7]);

    const int NQ = N_EDGES_C / 4;      // quad count
    const int NCHUNK = 4;
    int chunk = (NQ + NCHUNK - 1) / NCHUNK;
    for (int i = 0; i < NCHUNK; ++i) {
        int s = i * chunk;
        int e = s + chunk; if (e > NQ) e = NQ;
        edge_kernel<<<592, 128>>>(nodes, edges, senders, receivers, s, e);
    }
    node_kernel<<<148, 256>>>(nodes, graph_ids,
                              w[8], w[9], w[10], w[11],
                              w[12], w[13], w[14], w[15]);
    graph_kernel<<<32, 32>>>(w[16], w[17], w[18], w[19], (float*)d_out);
}

// round 10
// speedup vs baseline: 1.0917x; 1.0917x over previous
#include <cuda_runtime.h>
#include <cstdint>

#define N_NODES_C  500000
#define N_EDGES_C  8000000
#define N_GRAPHS_C 1000

#define LOG2E_F 1.4426950408889634f
#define SALPHA_F 1.7580993408473766f          // scale*alpha
#define SLN2_F   0.7282895255054788f          // scale*ln(2)

// Scratch (no cudaMalloc allowed)
__device__ float d_eon[N_NODES_C];
__device__ float d_g[N_GRAPHS_C * 11];
__device__ __align__(16) float d_EW[96];      // folded edge-stage weights (exp2-space)

__device__ __forceinline__ float ex2(float y) {
    float r;
    asm("ex2.approx.f32 %0, %1;" : "=f"(r) : "f"(y));
    return r;
}
// selu from y = x*log2(e):  selu(x) = s*ln2*max(y,0) + s*a*(2^min(y,0) - 1)
__device__ __forceinline__ float selu_y(float y) {
    float e   = ex2(fminf(y, 0.0f));
    float lin = fmaxf(y, 0.0f);
    return fmaf(SALPHA_F, e, fmaf(SLN2_F, lin, -SALPHA_F));
}

// ---------------------------------------------------------------------------
// Fused: zero d_eon/d_g (all blocks) + fold edge-stage weights (block 0).
// d_EW layout:
//   [0:20)  pn_w1*L       [20:30) pn_b1*L
//   [30:80) M*L (M = pn_w2 @ ue_w1[1:,:])   [80:85) d*L
//   [85:90) ue_w1[0,:]*L  [90:95) ue_w2     [95] ue_b2
// ---------------------------------------------------------------------------
__global__ void zero_and_setup(const float* __restrict__ pn_w1, const float* __restrict__ pn_b1,
                               const float* __restrict__ pn_w2, const float* __restrict__ pn_b2,
                               const float* __restrict__ ue_w1, const float* __restrict__ ue_b1,
                               const float* __restrict__ ue_w2, const float* __restrict__ ue_b2) {
    if (blockIdx.x == 0) {
        int t = threadIdx.x;
        if (t < 20) d_EW[t] = pn_w1[t] * LOG2E_F;
        if (t < 10) d_EW[20 + t] = pn_b1[t] * LOG2E_F;
        if (t < 50) {
            int j = t / 5, k = t % 5;
            float m = 0.0f;
            for (int q = 0; q < 10; ++q)
                m += pn_w2[j * 10 + q] * ue_w1[(1 + q) * 5 + k];
            d_EW[30 + t] = m * LOG2E_F;
        }
        if (t < 5) {
            float dd = ue_b1[t];
            for (int q = 0; q < 10; ++q)
                dd += pn_b2[q] * ue_w1[(1 + q) * 5 + t];
            d_EW[80 + t] = dd * LOG2E_F;
            d_EW[85 + t] = ue_w1[t] * LOG2E_F;
            d_EW[90 + t] = ue_w2[t];
        }
        if (t == 0) d_EW[95] = ue_b2[0];
    }
    int i = blockIdx.x * blockDim.x + threadIdx.x;
    int stride = gridDim.x * blockDim.x;
    float4* p = reinterpret_cast<float4*>(d_eon);
    for (int k = i; k < N_NODES_C / 4; k += stride)
        p[k] = make_float4(0.f, 0.f, 0.f, 0.f);
    for (int k = i; k < N_GRAPHS_C * 11; k += stride)
        d_g[k] = 0.f;
}

// ---------------------------------------------------------------------------
// Edge stage (R7 body — best measured): 4 adjacent edges/thread, int4/float4
// loads, 8 random gathers in flight, M matrix in shared (broadcast LDS).
// 4 blocks/SM x 128 => 16 warps, reg cap 128, no spill.
// Operates on QUAD indices [qstart, qend).
// ---------------------------------------------------------------------------
__global__ __launch_bounds__(128, 4) void edge_kernel(
        const float* __restrict__ nodes, const float* __restrict__ edges,
        const int* __restrict__ senders, const int* __restrict__ receivers,
        int qstart, int qend) {
    __shared__ __align__(16) float sM[10][8];   // M[j][0..4], padded row=32B

    int t = threadIdx.x;
    if (t < 50) sM[t / 5][t % 5] = d_EW[30 + t];

    float WA[10], WB[10], WC[10];
    float D[5], U[5], V[5], B2;
#pragma unroll
    for (int j = 0; j < 10; ++j) {
        WA[j] = __ldg(d_EW + j);
        WB[j] = __ldg(d_EW + 10 + j);
        WC[j] = __ldg(d_EW + 20 + j);
    }
#pragma unroll
    for (int q = 0; q < 5; ++q) {
        D[q] = __ldg(d_EW + 80 + q);
        U[q] = __ldg(d_EW + 85 + q);
        V[q] = __ldg(d_EW + 90 + q);
    }
    B2 = __ldg(d_EW + 95);
    __syncthreads();

    const int4*   r4p = (const int4*)receivers;
    const int4*   s4p = (const int4*)senders;
    const float4* e4p = (const float4*)edges;

    const int stride = gridDim.x * blockDim.x;
    for (int q = qstart + blockIdx.x * blockDim.x + threadIdx.x; q < qend; q += stride) {
        int4   rr = __ldg(r4p + q);
        int4   ss = __ldg(s4p + q);
        float4 ee = __ldg(e4p + q);

        // all 8 random gathers in flight before any compute
        float nr0 = __ldg(nodes + rr.x);
        float ns0 = __ldg(nodes + ss.x);
        float nr1 = __ldg(nodes + rr.y);
        float ns1 = __ldg(nodes + ss.y);
        float nr2 = __ldg(nodes + rr.z);
        float ns2 = __ldg(nodes + ss.z);
        float nr3 = __ldg(nodes + rr.w);
        float ns3 = __ldg(nodes + ss.w);

        float c0[5], c1[5], c2[5], c3[5];
#pragma unroll
        for (int k = 0; k < 5; ++k) { c0[k] = D[k]; c1[k] = D[k]; c2[k] = D[k]; c3[k] = D[k]; }

#pragma unroll
        for (int j = 0; j < 10; ++j) {
            float h0 = selu_y(fmaf(nr0, WA[j], fmaf(ns0, WB[j], WC[j])));
            float h1 = selu_y(fmaf(nr1, WA[j], fmaf(ns1, WB[j], WC[j])));
            float h2 = selu_y(fmaf(nr2, WA[j], fmaf(ns2, WB[j], WC[j])));
            float h3 = selu_y(fmaf(nr3, WA[j], fmaf(ns3, WB[j], WC[j])));
            float4 m4 = *reinterpret_cast<const float4*>(&sM[j][0]);
            float  m4e = sM[j][4];
            c0[0] = fmaf(h0, m4.x, c0[0]); c1[0] = fmaf(h1, m4.x, c1[0]);
            c2[0] = fmaf(h2, m4.x, c2[0]); c3[0] = fmaf(h3, m4.x, c3[0]);
            c0[1] = fmaf(h0, m4.y, c0[1]); c1[1] = fmaf(h1, m4.y, c1[1]);
            c2[1] = fmaf(h2, m4.y, c2[1]); c3[1] = fmaf(h3, m4.y, c3[1]);
            c0[2] = fmaf(h0, m4.z, c0[2]); c1[2] = fmaf(h1, m4.z, c1[2]);
            c2[2] = fmaf(h2, m4.z, c2[2]); c3[2] = fmaf(h3, m4.z, c3[2]);
            c0[3] = fmaf(h0, m4.w, c0[3]); c1[3] = fmaf(h1, m4.w, c1[3]);
            c2[3] = fmaf(h2, m4.w, c2[3]); c3[3] = fmaf(h3, m4.w, c3[3]);
            c0[4] = fmaf(h0, m4e, c0[4]);  c1[4] = fmaf(h1, m4e, c1[4]);
            c2[4] = fmaf(h2, m4e, c2[4]);  c3[4] = fmaf(h3, m4e, c3[4]);
        }

        float ev0 = ee.x, ev1 = ee.y, ev2 = ee.z, ev3 = ee.w;
#pragma unroll
        for (int it = 0; it < 3; ++it) {
            float a0 = B2, a1 = B2, a2 = B2, a3 = B2;
#pragma unroll
            for (int k = 0; k < 5; ++k) {
                a0 = fmaf(selu_y(fmaf(ev0, U[k], c0[k])), V[k], a0);
                a1 = fmaf(selu_y(fmaf(ev1, U[k], c1[k])), V[k], a1);
                a2 = fmaf(selu_y(fmaf(ev2, U[k], c2[k])), V[k], a2);
                a3 = fmaf(selu_y(fmaf(ev3, U[k], c3[k])), V[k], a3);
            }
            ev0 = a0; ev1 = a1; ev2 = a2; ev3 = a3;
        }
        atomicAdd(&d_eon[rr.x], ev0);
        atomicAdd(&d_eon[rr.y], ev1);
        atomicAdd(&d_eon[rr.z], ev2);
        atomicAdd(&d_eon[rr.w], ev3);
    }
}

// ---------------------------------------------------------------------------
// Node stage: pe MLP + 3 un iterations, warp-aggregated segment sum into d_g.
// ---------------------------------------------------------------------------
__global__ __launch_bounds__(256) void node_kernel(
        const float* __restrict__ nodes, const int* __restrict__ graph_ids,
        const float* __restrict__ pe_w1, const float* __restrict__ pe_b1,
        const float* __restrict__ pe_w2, const float* __restrict__ pe_b2,
        const float* __restrict__ un_w1, const float* __restrict__ un_b1,
        const float* __restrict__ un_w2, const float* __restrict__ un_b2) {
    float PW1[5], PB1[5], PW2[50], PB2[10];
    float UW1[55], UB1[5], UW2[5], UB2v;
#pragma unroll
    for (int i = 0; i < 5; ++i) {
        PW1[i] = __ldg(pe_w1 + i) * LOG2E_F;
        PB1[i] = __ldg(pe_b1 + i) * LOG2E_F;
        UB1[i] = __ldg(un_b1 + i) * LOG2E_F;
        UW2[i] = __ldg(un_w2 + i);
    }
#pragma unroll
    for (int i = 0; i < 50; ++i) PW2[i] = __ldg(pe_w2 + i);
#pragma unroll
    for (int i = 0; i < 10; ++i) PB2[i] = __ldg(pe_b2 + i);
#pragma unroll
    for (int i = 0; i < 55; ++i) UW1[i] = __ldg(un_w1 + i) * LOG2E_F;
    UB2v = __ldg(un_b2);

    int stride = gridDim.x * blockDim.x;
    for (int n = blockIdx.x * blockDim.x + threadIdx.x; n < N_NODES_C; n += stride) {
        float eon = d_eon[n];
        float v[11];
        float hid[5];
#pragma unroll
        for (int k = 0; k < 5; ++k) hid[k] = selu_y(fmaf(eon, PW1[k], PB1[k]));
#pragma unroll
        for (int j = 0; j < 10; ++j) {
            float acc = PB2[j];
#pragma unroll
            for (int k = 0; k < 5; ++k) acc = fmaf(hid[k], PW2[k * 10 + j], acc);
            v[1 + j] = acc;
        }
        float c[5];
#pragma unroll
        for (int k = 0; k < 5; ++k) {
            float acc = UB1[k];
#pragma unroll
            for (int t = 0; t < 10; ++t) acc = fmaf(v[1 + t], UW1[(1 + t) * 5 + k], acc);
            c[k] = acc;
        }
        float x = nodes[n];
#pragma unroll
        for (int it = 0; it < 3; ++it) {
            float acc = UB2v;
#pragma unroll
            for (int k = 0; k < 5; ++k)
                acc = fmaf(selu_y(fmaf(x, UW1[k], c[k])), UW2[k], acc);
            x = acc;
        }
        v[0] = x;

        int gid = graph_ids[n];
        const unsigned mask = 0xffffffffu;
        int g0 = __shfl_sync(mask, gid, 0);
        bool uni = __all_sync(mask, gid == g0);
        if (uni) {
#pragma unroll
            for (int j = 0; j < 11; ++j) {
                float vv = v[j];
#pragma unroll
                for (int off = 16; off > 0; off >>= 1)
                    vv += __shfl_down_sync(mask, vv, off);
                if ((threadIdx.x & 31) == 0) atomicAdd(&d_g[g0 * 11 + j], vv);
            }
        } else {
#pragma unroll
            for (int j = 0; j < 11; ++j)
                atomicAdd(&d_g[gid * 11 + j], v[j]);
        }
    }
}

// ---------------------------------------------------------------------------
__global__ void graph_kernel(const float* __restrict__ pr_w1, const float* __restrict__ pr_b1,
                             const float* __restrict__ pr_w2, const float* __restrict__ pr_b2,
                             float* __restrict__ out) {
    int g = blockIdx.x * blockDim.x + threadIdx.x;
    if (g >= N_GRAPHS_C) return;
    float gv[11];
#pragma unroll
    for (int i = 0; i < 11; ++i) gv[i] = d_g[g * 11 + i];
    float hid[10];
#pragma unroll
    for (int j = 0; j < 10; ++j) {
        float acc = __ldg(pr_b1 + j) * LOG2E_F;
#pragma unroll
        for (int i = 0; i < 11; ++i)
            acc = fmaf(gv[i], __ldg(pr_w1 + i * 10 + j) * LOG2E_F, acc);
        hid[j] = selu_y(acc);
    }
    float o[10];
    float mx = -1e30f;
#pragma unroll
    for (int k = 0; k < 10; ++k) {
        float acc = __ldg(pr_b2 + k) * LOG2E_F;
#pragma unroll
        for (int j = 0; j < 10; ++j)
            acc = fmaf(hid[j], __ldg(pr_w2 + j * 10 + k) * LOG2E_F, acc);
        o[k] = acc;
        mx = fmaxf(mx, acc);
    }
    float sum = 0.0f;
#pragma unroll
    for (int k = 0; k < 10; ++k) { o[k] = ex2(o[k] - mx); sum += o[k]; }
    float inv = 1.0f / sum;
#pragma unroll
    for (int k = 0; k < 10; ++k) out[g * 10 + k] = o[k] * inv;
}

// ---------------------------------------------------------------------------
extern "C" void kernel_launch(void* const* d_in, const int* in_sizes, int n_in,
                              void* d_out, int out_size) {
    const float* nodes = (const float*)d_in[0];
    const float* edges = (const float*)d_in[1];
    const int *senders, *receivers, *graph_ids;
    const float* w[20];

    if (in_sizes[2] == N_EDGES_C) {
        senders   = (const int*)d_in[2];
        receivers = (const int*)d_in[3];
        graph_ids = (const int*)d_in[4];
        int base = (n_in > 25 && in_sizes[5] == 1) ? 6 : 5;
        for (int i = 0; i < 20; ++i) w[i] = (const float*)d_in[base + i];
    } else {
        for (int i = 0; i < 20; ++i) w[i] = (const float*)d_in[2 + i];
        senders   = (const int*)d_in[22];
        receivers = (const int*)d_in[23];
        graph_ids = (const int*)d_in[24];
    }

    // Launch order: fused zero+setup(0), edge halves(1,2), node(3), graph(4).
    zero_and_setup<<<232, 256>>>(w[0], w[1], w[2], w[3], w[4], w[5], w[6], w[7]);

    const int NQ = N_EDGES_C / 4;      // quad count
    const int NCHUNK = 2;
    int chunk = (NQ + NCHUNK - 1) / NCHUNK;
    for (int i = 0; i < NCHUNK; ++i) {
        int s = i * chunk;
        int e = s + chunk; if (e > NQ) e = NQ;
        edge_kernel<<<592, 128>>>(nodes, edges, senders, receivers, s, e);
    }
    node_kernel<<<148, 256>>>(nodes, graph_ids,
                              w[8], w[9], w[10], w[11],
                              w[12], w[13], w[14], w[15]);
    graph_kernel<<<32, 32>>>(w[16], w[17], w[18], w[19], (float*)d_out);
}

// round 11
// speedup vs baseline: 1.2694x; 1.1628x over previous
#include <cuda_runtime.h>
#include <cstdint>

#define N_NODES_C  500000
#define N_EDGES_C  8000000
#define N_GRAPHS_C 1000

#define LOG2E_F 1.4426950408889634f
#define SALPHA_F 1.7580993408473766f          // scale*alpha
#define SLN2_F   0.7282895255054788f          // scale*ln(2)

// Scratch (no cudaMalloc allowed)
__device__ float d_eon[N_NODES_C];
__device__ float d_g[N_GRAPHS_C * 8];         // per-graph: x-sum, hid-sum[5], count, pad
__device__ __align__(16) float d_EW[96];      // folded edge-stage weights (exp2-space)
__device__ __align__(16) float d_NW[64];      // folded node-stage weights (exp2-space)

__device__ __forceinline__ float ex2(float y) {
    float r;
    asm("ex2.approx.f32 %0, %1;" : "=f"(r) : "f"(y));
    return r;
}
// selu from y = x*log2(e):  selu(x) = s*ln2*max(y,0) + s*a*(2^min(y,0) - 1)
__device__ __forceinline__ float selu_y(float y) {
    float e   = ex2(fminf(y, 0.0f));
    float lin = fmaxf(y, 0.0f);
    return fmaf(SALPHA_F, e, fmaf(SLN2_F, lin, -SALPHA_F));
}

// ---------------------------------------------------------------------------
// Fused: zero scratch (all blocks) + fold edge/node weights (block 0).
// d_EW: [0:20) pn_w1*L  [20:30) pn_b1*L  [30:80) M*L  [80:85) d*L
//       [85:90) ue_w1[0,:]*L  [90:95) ue_w2  [95] ue_b2
// d_NW: [0:5) pe_w1*L  [5:10) pe_b1*L  [10:35) M2*L (pe_w2@un_w1[1:])
//       [35:40) D2*L   [40:45) un_w1[0,:]*L  [45:50) un_w2  [50] un_b2
// ---------------------------------------------------------------------------
__global__ void zero_and_setup(
        const float* __restrict__ pn_w1, const float* __restrict__ pn_b1,
        const float* __restrict__ pn_w2, const float* __restrict__ pn_b2,
        const float* __restrict__ ue_w1, const float* __restrict__ ue_b1,
        const float* __restrict__ ue_w2, const float* __restrict__ ue_b2,
        const float* __restrict__ pe_w1, const float* __restrict__ pe_b1,
        const float* __restrict__ pe_w2, const float* __restrict__ pe_b2,
        const float* __restrict__ un_w1, const float* __restrict__ un_b1,
        const float* __restrict__ un_w2, const float* __restrict__ un_b2) {
    if (blockIdx.x == 0) {
        int t = threadIdx.x;
        // ---- edge-stage folds ----
        if (t < 20) d_EW[t] = pn_w1[t] * LOG2E_F;
        if (t < 10) d_EW[20 + t] = pn_b1[t] * LOG2E_F;
        if (t < 50) {
            int j = t / 5, k = t % 5;
            float m = 0.0f;
            for (int q = 0; q < 10; ++q)
                m += pn_w2[j * 10 + q] * ue_w1[(1 + q) * 5 + k];
            d_EW[30 + t] = m * LOG2E_F;
        }
        if (t < 5) {
            float dd = ue_b1[t];
            for (int q = 0; q < 10; ++q)
                dd += pn_b2[q] * ue_w1[(1 + q) * 5 + t];
            d_EW[80 + t] = dd * LOG2E_F;
            d_EW[85 + t] = ue_w1[t] * LOG2E_F;
            d_EW[90 + t] = ue_w2[t];
        }
        if (t == 0) d_EW[95] = ue_b2[0];
        // ---- node-stage folds ----
        if (t < 5) {
            d_NW[t]      = pe_w1[t] * LOG2E_F;
            d_NW[5 + t]  = pe_b1[t] * LOG2E_F;
            float dd = un_b1[t];
            for (int j = 0; j < 10; ++j)
                dd += pe_b2[j] * un_w1[(1 + j) * 5 + t];
            d_NW[35 + t] = dd * LOG2E_F;
            d_NW[40 + t] = un_w1[t] * LOG2E_F;
            d_NW[45 + t] = un_w2[t];
        }
        if (t < 25) {
            int q = t / 5, k = t % 5;
            float m = 0.0f;
            for (int j = 0; j < 10; ++j)
                m += pe_w2[q * 10 + j] * un_w1[(1 + j) * 5 + k];
            d_NW[10 + t] = m * LOG2E_F;
        }
        if (t == 0) d_NW[50] = un_b2[0];
    }
    int i = blockIdx.x * blockDim.x + threadIdx.x;
    int stride = gridDim.x * blockDim.x;
    float4* p = reinterpret_cast<float4*>(d_eon);
    for (int k = i; k < N_NODES_C / 4; k += stride)
        p[k] = make_float4(0.f, 0.f, 0.f, 0.f);
    for (int k = i; k < N_GRAPHS_C * 8; k += stride)
        d_g[k] = 0.f;
}

// ---------------------------------------------------------------------------
// Edge stage (best-measured R7 body): 4 adjacent edges/thread, 8 gathers in
// flight, M in shared. 4 blocks/SM x 128 thr. QUAD indices [qstart, qend).
// ---------------------------------------------------------------------------
__global__ __launch_bounds__(128, 4) void edge_kernel(
        const float* __restrict__ nodes, const float* __restrict__ edges,
        const int* __restrict__ senders, const int* __restrict__ receivers,
        int qstart, int qend) {
    __shared__ __align__(16) float sM[10][8];

    int t = threadIdx.x;
    if (t < 50) sM[t / 5][t % 5] = d_EW[30 + t];

    float WA[10], WB[10], WC[10];
    float D[5], U[5], V[5], B2;
#pragma unroll
    for (int j = 0; j < 10; ++j) {
        WA[j] = __ldg(d_EW + j);
        WB[j] = __ldg(d_EW + 10 + j);
        WC[j] = __ldg(d_EW + 20 + j);
    }
#pragma unroll
    for (int q = 0; q < 5; ++q) {
        D[q] = __ldg(d_EW + 80 + q);
        U[q] = __ldg(d_EW + 85 + q);
        V[q] = __ldg(d_EW + 90 + q);
    }
    B2 = __ldg(d_EW + 95);
    __syncthreads();

    const int4*   r4p = (const int4*)receivers;
    const int4*   s4p = (const int4*)senders;
    const float4* e4p = (const float4*)edges;

    const int stride = gridDim.x * blockDim.x;
    for (int q = qstart + blockIdx.x * blockDim.x + threadIdx.x; q < qend; q += stride) {
        int4   rr = __ldg(r4p + q);
        int4   ss = __ldg(s4p + q);
        float4 ee = __ldg(e4p + q);

        float nr0 = __ldg(nodes + rr.x);
        float ns0 = __ldg(nodes + ss.x);
        float nr1 = __ldg(nodes + rr.y);
        float ns1 = __ldg(nodes + ss.y);
        float nr2 = __ldg(nodes + rr.z);
        float ns2 = __ldg(nodes + ss.z);
        float nr3 = __ldg(nodes + rr.w);
        float ns3 = __ldg(nodes + ss.w);

        float c0[5], c1[5], c2[5], c3[5];
#pragma unroll
        for (int k = 0; k < 5; ++k) { c0[k] = D[k]; c1[k] = D[k]; c2[k] = D[k]; c3[k] = D[k]; }

#pragma unroll
        for (int j = 0; j < 10; ++j) {
            float h0 = selu_y(fmaf(nr0, WA[j], fmaf(ns0, WB[j], WC[j])));
            float h1 = selu_y(fmaf(nr1, WA[j], fmaf(ns1, WB[j], WC[j])));
            float h2 = selu_y(fmaf(nr2, WA[j], fmaf(ns2, WB[j], WC[j])));
            float h3 = selu_y(fmaf(nr3, WA[j], fmaf(ns3, WB[j], WC[j])));
            float4 m4 = *reinterpret_cast<const float4*>(&sM[j][0]);
            float  m4e = sM[j][4];
            c0[0] = fmaf(h0, m4.x, c0[0]); c1[0] = fmaf(h1, m4.x, c1[0]);
            c2[0] = fmaf(h2, m4.x, c2[0]); c3[0] = fmaf(h3, m4.x, c3[0]);
            c0[1] = fmaf(h0, m4.y, c0[1]); c1[1] = fmaf(h1, m4.y, c1[1]);
            c2[1] = fmaf(h2, m4.y, c2[1]); c3[1] = fmaf(h3, m4.y, c3[1]);
            c0[2] = fmaf(h0, m4.z, c0[2]); c1[2] = fmaf(h1, m4.z, c1[2]);
            c2[2] = fmaf(h2, m4.z, c2[2]); c3[2] = fmaf(h3, m4.z, c3[2]);
            c0[3] = fmaf(h0, m4.w, c0[3]); c1[3] = fmaf(h1, m4.w, c1[3]);
            c2[3] = fmaf(h2, m4.w, c2[3]); c3[3] = fmaf(h3, m4.w, c3[3]);
            c0[4] = fmaf(h0, m4e, c0[4]);  c1[4] = fmaf(h1, m4e, c1[4]);
            c2[4] = fmaf(h2, m4e, c2[4]);  c3[4] = fmaf(h3, m4e, c3[4]);
        }

        float ev0 = ee.x, ev1 = ee.y, ev2 = ee.z, ev3 = ee.w;
#pragma unroll
        for (int it = 0; it < 3; ++it) {
            float a0 = B2, a1 = B2, a2 = B2, a3 = B2;
#pragma unroll
            for (int k = 0; k < 5; ++k) {
                a0 = fmaf(selu_y(fmaf(ev0, U[k], c0[k])), V[k], a0);
                a1 = fmaf(selu_y(fmaf(ev1, U[k], c1[k])), V[k], a1);
                a2 = fmaf(selu_y(fmaf(ev2, U[k], c2[k])), V[k], a2);
                a3 = fmaf(selu_y(fmaf(ev3, U[k], c3[k])), V[k], a3);
            }
            ev0 = a0; ev1 = a1; ev2 = a2; ev3 = a3;
        }
        atomicAdd(&d_eon[rr.x], ev0);
        atomicAdd(&d_eon[rr.y], ev1);
        atomicAdd(&d_eon[rr.z], ev2);
        atomicAdd(&d_eon[rr.w], ev3);
    }
}

// ---------------------------------------------------------------------------
// Node stage (folded): hid = selu(eon*pw1+pb1); c = D2 + hid@M2;
// x-loop 3 iters; accumulate {x, hid[0..4], 1} per graph (pe_w2 applied later).
// 51 weight regs, 3 blocks/SM x 256 => 24 warps.
// ---------------------------------------------------------------------------
__global__ __launch_bounds__(256, 3) void node_kernel(
        const float* __restrict__ nodes, const int* __restrict__ graph_ids) {
    float W[51];
#pragma unroll
    for (int i = 0; i < 51; ++i) W[i] = __ldg(d_NW + i);

    int stride = gridDim.x * blockDim.x;
    for (int n = blockIdx.x * blockDim.x + threadIdx.x; n < N_NODES_C; n += stride) {
        float eon = d_eon[n];
        float hid[5];
#pragma unroll
        for (int k = 0; k < 5; ++k)
            hid[k] = selu_y(fmaf(eon, W[k], W[5 + k]));
        float c[5];
#pragma unroll
        for (int k = 0; k < 5; ++k) {
            float acc = W[35 + k];
#pragma unroll
            for (int q = 0; q < 5; ++q)
                acc = fmaf(hid[q], W[10 + q * 5 + k], acc);
            c[k] = acc;
        }
        float x = nodes[n];
#pragma unroll
        for (int it = 0; it < 3; ++it) {
            float acc = W[50];
#pragma unroll
            for (int k = 0; k < 5; ++k)
                acc = fmaf(selu_y(fmaf(x, W[40 + k], c[k])), W[45 + k], acc);
            x = acc;
        }

        float v[7];
        v[0] = x;
#pragma unroll
        for (int k = 0; k < 5; ++k) v[1 + k] = hid[k];
        v[6] = 1.0f;

        int gid = graph_ids[n];
        const unsigned mask = 0xffffffffu;
        int g0 = __shfl_sync(mask, gid, 0);
        bool uni = __all_sync(mask, gid == g0);
        if (uni) {
#pragma unroll
            for (int j = 0; j < 7; ++j) {
                float vv = v[j];
#pragma unroll
                for (int off = 16; off > 0; off >>= 1)
                    vv += __shfl_down_sync(mask, vv, off);
                if ((threadIdx.x & 31) == 0) atomicAdd(&d_g[g0 * 8 + j], vv);
            }
        } else {
#pragma unroll
            for (int j = 0; j < 7; ++j)
                atomicAdd(&d_g[gid * 8 + j], v[j]);
        }
    }
}

// ---------------------------------------------------------------------------
// Final: reconstruct g[11] (x-sum, cnt*pe_b2 + hidsum@pe_w2), pr MLP, softmax.
// Weights staged in shared per block.
// ---------------------------------------------------------------------------
__global__ __launch_bounds__(128) void graph_kernel(
        const float* __restrict__ pe_w2, const float* __restrict__ pe_b2,
        const float* __restrict__ pr_w1, const float* __restrict__ pr_b1,
        const float* __restrict__ pr_w2, const float* __restrict__ pr_b2,
        float* __restrict__ out) {
    __shared__ float sPE2[50], sPEB[10];
    __shared__ float sW1[110], sB1[10], sW2[100], sB2[10];
    int t = threadIdx.x;
    if (t < 50)  sPE2[t] = pe_w2[t];
    if (t < 10)  sPEB[t] = pe_b2[t];
    if (t < 110) sW1[t] = pr_w1[t] * LOG2E_F;
    if (t < 10)  sB1[t] = pr_b1[t] * LOG2E_F;
    if (t < 100) sW2[t] = pr_w2[t] * LOG2E_F;
    if (t < 10)  sB2[t] = pr_b2[t] * LOG2E_F;
    __syncthreads();

    int g = blockIdx.x * blockDim.x + threadIdx.x;
    if (g >= N_GRAPHS_C) return;

    float gv[11];
    gv[0] = d_g[g * 8 + 0];
    float hs[5], cnt = d_g[g * 8 + 6];
#pragma unroll
    for (int q = 0; q < 5; ++q) hs[q] = d_g[g * 8 + 1 + q];
#pragma unroll
    for (int j = 0; j < 10; ++j) {
        float acc = cnt * sPEB[j];
#pragma unroll
        for (int q = 0; q < 5; ++q) acc = fmaf(hs[q], sPE2[q * 10 + j], acc);
        gv[1 + j] = acc;
    }

    float hid[10];
#pragma unroll
    for (int j = 0; j < 10; ++j) {
        float acc = sB1[j];
#pragma unroll
        for (int i = 0; i < 11; ++i) acc = fmaf(gv[i], sW1[i * 10 + j], acc);
        hid[j] = selu_y(acc);
    }
    float o[10];
    float mx = -1e30f;
#pragma unroll
    for (int k = 0; k < 10; ++k) {
        float acc = sB2[k];
#pragma unroll
        for (int j = 0; j < 10; ++j) acc = fmaf(hid[j], sW2[j * 10 + k], acc);
        o[k] = acc;
        mx = fmaxf(mx, acc);
    }
    float sum = 0.0f;
#pragma unroll
    for (int k = 0; k < 10; ++k) { o[k] = ex2(o[k] - mx); sum += o[k]; }
    float inv = 1.0f / sum;
#pragma unroll
    for (int k = 0; k < 10; ++k) out[g * 10 + k] = o[k] * inv;
}

// ---------------------------------------------------------------------------
extern "C" void kernel_launch(void* const* d_in, const int* in_sizes, int n_in,
                              void* d_out, int out_size) {
    const float* nodes = (const float*)d_in[0];
    const float* edges = (const float*)d_in[1];
    const int *senders, *receivers, *graph_ids;
    const float* w[20];

    if (in_sizes[2] == N_EDGES_C) {
        senders   = (const int*)d_in[2];
        receivers = (const int*)d_in[3];
        graph_ids = (const int*)d_in[4];
        int base = (n_in > 25 && in_sizes[5] == 1) ? 6 : 5;
        for (int i = 0; i < 20; ++i) w[i] = (const float*)d_in[base + i];
    } else {
        for (int i = 0; i < 20; ++i) w[i] = (const float*)d_in[2 + i];
        senders   = (const int*)d_in[22];
        receivers = (const int*)d_in[23];
        graph_ids = (const int*)d_in[24];
    }

    zero_and_setup<<<232, 256>>>(w[0], w[1], w[2], w[3], w[4], w[5], w[6], w[7],
                                 w[8], w[9], w[10], w[11], w[12], w[13], w[14], w[15]);

    const int NQ = N_EDGES_C / 4;      // quad count
    const int NCHUNK = 2;
    int chunk = (NQ + NCHUNK - 1) / NCHUNK;
    for (int i = 0; i < NCHUNK; ++i) {
        int s = i * chunk;
        int e = s + chunk; if (e > NQ) e = NQ;
        edge_kernel<<<592, 128>>>(nodes, edges, senders, receivers, s, e);
    }
    node_kernel<<<444, 256>>>(nodes, graph_ids);
    graph_kernel<<<8, 128>>>(w[10], w[11], w[16], w[17], w[18], w[19], (float*)d_out);
}